// round 11
// baseline (speedup 1.0000x reference)
#include <cuda_runtime.h>
#include <cuda_bf16.h>
#include <cstdint>

#define D       128
#define MAXN    100000
#define MAXE    1600000

typedef unsigned long long u64;

// ---------------------------------------------------------------------------
// Scratch — static __device__ arrays, referenced ONLY inside kernels.
// (NEVER pass these as kernel args: host shadow symbol + GB300 ATS = silent
//  NVLink-C2C traffic — the round-2/4 5ms regression.)
// ---------------------------------------------------------------------------
__device__ int   g_deg[MAXN];
__device__ float g_scale[MAXN];                    // rsqrt(deg+1)
__device__ float g_inv[MAXN];                      // 1/max(deg,1)
__device__ int   g_rowstart[MAXN];
__device__ int   g_cursor[MAXN];
__device__ int   g_csr[MAXE];                      // src ids grouped by dst
__device__ int   g_total;                          // rowstart allocator
__device__ float g_pre[(size_t)MAXN * D];          // scale*(feat @ W)  (51.2MB)

// ---------------------------------------------------------------------------
// 0) In-degree histogram (g_deg zeroed by previous replay's agg tail)
// ---------------------------------------------------------------------------
__global__ void deg_kernel(const int* __restrict__ dst, int E) {
    int i = blockIdx.x * blockDim.x + threadIdx.x;
    if (i < E) atomicAdd(&g_deg[dst[i]], 1);
}

// ---------------------------------------------------------------------------
// 1) mini-prep: scale, inv, rowstart, cursor
// ---------------------------------------------------------------------------
__global__ void prep_kernel(int N) {
    int i = blockIdx.x * blockDim.x + threadIdx.x;
    if (i >= N) return;
    int dg = g_deg[i];
    g_scale[i] = rsqrtf((float)dg + 1.0f);
    g_inv[i]   = 1.0f / (float)(dg > 0 ? dg : 1);
    int rs = atomicAdd(&g_total, dg);
    g_rowstart[i] = rs;
    g_cursor[i]   = rs;
}

// ---------------------------------------------------------------------------
// 2) CSR fill: bucket src by dst
// ---------------------------------------------------------------------------
__global__ void fill_kernel(const int* __restrict__ src,
                            const int* __restrict__ dst, int E) {
    int i = blockIdx.x * blockDim.x + threadIdx.x;
    if (i < E) {
        int p = atomicAdd(&g_cursor[dst[i]], 1);
        g_csr[p] = src[i];
    }
}

// ---------------------------------------------------------------------------
// 3) GEMM: g_pre[m,:] = scale[m] * (feat[m,:] @ W)
//    FFMA2 with duplicated-W smem (zero pack movs) and transposed A tile
//    (row-pair LDS.128). Inner loop: 2+4 LDS.128 + 32 FFMA2 per k.
// ---------------------------------------------------------------------------
#define BM 128
#define BN 128
#define BK 32
#define AK 132                  // A row pitch: 128+4 floats -> 16B-aligned rows
#define WK 260                  // Ws2 row pitch: 256+4 floats (16B-aligned, stagger)

__device__ __forceinline__ float2 unpack2(u64 v) {
    float2 r;
    asm("mov.b64 {%0,%1}, %2;" : "=f"(r.x), "=f"(r.y) : "l"(v));
    return r;
}
__device__ __forceinline__ void fma2(u64& c, u64 a, u64 b) {
    asm("fma.rn.f32x2 %0, %1, %2, %3;" : "=l"(c) : "l"(a), "l"(b), "l"(c));
}

__global__ __launch_bounds__(256)
void gemm_kernel(const float* __restrict__ feat,
                 const float* __restrict__ W,
                 int n) {
    __shared__ __align__(16) float As[BK][AK];       // 32*132*4 = 16.9KB
    __shared__ __align__(16) float Ws2[BK][WK];      // 32*260*4 = 33.3KB

    int block_row = blockIdx.x * BM;
    int tid = threadIdx.x;
    int tx = tid & 15;          // col group (8 cols)
    int ty = tid >> 4;          // row group (8 rows)

    u64 c2[4][8];               // [row-pair p][col j]; lo=row 2p, hi=row 2p+1
#pragma unroll
    for (int p = 0; p < 4; p++)
#pragma unroll
        for (int j = 0; j < 8; j++) c2[p][j] = 0ULL;

    for (int k0 = 0; k0 < D; k0 += BK) {
        // A tile: feat[BM][BK] -> transposed As[k][row]
#pragma unroll
        for (int it = 0; it < 4; it++) {
            int idx = tid + it * 256;            // 0..1023
            int row = idx >> 3;                  // 0..127
            int k4  = (idx & 7) * 4;             // 0,4,...,28
            int grow = block_row + row;
            if (grow >= n) grow = n - 1;         // clamp; dup rows never stored
            float4 v = __ldg((const float4*)&feat[(size_t)grow * D + k0 + k4]);
            As[k4 + 0][row] = v.x;
            As[k4 + 1][row] = v.y;
            As[k4 + 2][row] = v.z;
            As[k4 + 3][row] = v.w;
        }
        // W tile duplicated: Ws2[k][2v]=Ws2[k][2v+1]=W[k0+k][v]
        {
            int k  = tid >> 3;                   // 0..31
            int nb = (tid & 7) * 16;             // 0,16,...,112
            const float4* wsrc = (const float4*)&W[(size_t)(k0 + k) * D + nb];
#pragma unroll
            for (int i = 0; i < 4; i++) {
                float4 w = __ldg(wsrc + i);
                int cbase = 2 * (nb + 4 * i);
                *(float4*)&Ws2[k][cbase]     = make_float4(w.x, w.x, w.y, w.y);
                *(float4*)&Ws2[k][cbase + 4] = make_float4(w.z, w.z, w.w, w.w);
            }
        }
        __syncthreads();

#pragma unroll 8
        for (int k = 0; k < BK; k++) {
            u64 ap[4], wd[8];
            const u64* apt = (const u64*)&As[k][ty * 8];
#pragma unroll
            for (int p = 0; p < 4; p++) ap[p] = apt[p];      // fuses to 2 LDS.128
            const u64* wpt = (const u64*)&Ws2[k][tx * 16];
#pragma unroll
            for (int j = 0; j < 8; j++) wd[j] = wpt[j];      // fuses to 4 LDS.128
#pragma unroll
            for (int p = 0; p < 4; p++)
#pragma unroll
                for (int j = 0; j < 8; j++)
                    fma2(c2[p][j], ap[p], wd[j]);
        }
        __syncthreads();
    }

    // Epilogue: apply per-row scale, store both rows of each pair
#pragma unroll
    for (int p = 0; p < 4; p++) {
        float2 f[8];
#pragma unroll
        for (int j = 0; j < 8; j++) f[j] = unpack2(c2[p][j]);
        int row0 = block_row + ty * 8 + 2 * p;
        int row1 = row0 + 1;
        int col  = tx * 8;
        if (row0 < n) {
            float sc = g_scale[row0];
            *(float4*)&g_pre[(size_t)row0 * D + col] =
                make_float4(f[0].x * sc, f[1].x * sc, f[2].x * sc, f[3].x * sc);
            *(float4*)&g_pre[(size_t)row0 * D + col + 4] =
                make_float4(f[4].x * sc, f[5].x * sc, f[6].x * sc, f[7].x * sc);
        }
        if (row1 < n) {
            float sc = g_scale[row1];
            *(float4*)&g_pre[(size_t)row1 * D + col] =
                make_float4(f[0].y * sc, f[1].y * sc, f[2].y * sc, f[3].y * sc);
            *(float4*)&g_pre[(size_t)row1 * D + col + 4] =
                make_float4(f[4].y * sc, f[5].y * sc, f[6].y * sc, f[7].y * sc);
        }
    }
}

// ---------------------------------------------------------------------------
// 4) Aggregation (gather): one warp per dst node; resets replay state.
// ---------------------------------------------------------------------------
__global__ __launch_bounds__(256)
void agg_kernel(const float* __restrict__ bias,
                float* __restrict__ out,
                int N) {
    int t = blockIdx.x * blockDim.x + threadIdx.x;
    int node = t >> 5;
    int lane = t & 31;
    if (node >= N) return;

    int start = g_rowstart[node];
    int deg   = g_deg[node];
    int end   = start + deg;

    const float4* pre4 = (const float4*)g_pre;

    float4 acc = make_float4(0.f, 0.f, 0.f, 0.f);

    int j = start;
    for (; j + 3 < end; j += 4) {
        int s0 = __ldg(&g_csr[j + 0]);
        int s1 = __ldg(&g_csr[j + 1]);
        int s2 = __ldg(&g_csr[j + 2]);
        int s3 = __ldg(&g_csr[j + 3]);
        float4 v0 = __ldg(pre4 + (size_t)s0 * 32 + lane);
        float4 v1 = __ldg(pre4 + (size_t)s1 * 32 + lane);
        float4 v2 = __ldg(pre4 + (size_t)s2 * 32 + lane);
        float4 v3 = __ldg(pre4 + (size_t)s3 * 32 + lane);
        acc.x += v0.x + v1.x + v2.x + v3.x;
        acc.y += v0.y + v1.y + v2.y + v3.y;
        acc.z += v0.z + v1.z + v2.z + v3.z;
        acc.w += v0.w + v1.w + v2.w + v3.w;
    }
    for (; j < end; j++) {
        int s = __ldg(&g_csr[j]);
        float4 v = __ldg(pre4 + (size_t)s * 32 + lane);
        acc.x += v.x; acc.y += v.y; acc.z += v.z; acc.w += v.w;
    }

    float iv = g_inv[node];
    float4 bb = __ldg((const float4*)bias + lane);
    float4 r;
    r.x = acc.x * iv + bb.x;
    r.y = acc.y * iv + bb.y;
    r.z = acc.z * iv + bb.z;
    r.w = acc.w * iv + bb.w;
    *((float4*)(out + (size_t)node * D) + lane) = r;

    // Reset per-replay state (node-private: this warp already consumed deg)
    if (lane == 0) g_deg[node] = 0;
    if (t == 0)    g_total = 0;
}

// ---------------------------------------------------------------------------
extern "C" void kernel_launch(void* const* d_in, const int* in_sizes, int n_in,
                              void* d_out, int out_size) {
    const float* feature = (const float*)d_in[0];
    const float* W       = (const float*)d_in[1];
    const float* bias    = (const float*)d_in[2];
    const int*   src     = (const int*)d_in[3];
    const int*   dst     = (const int*)d_in[4];
    float*       out     = (float*)d_out;

    int N = in_sizes[0] / D;
    int E = in_sizes[3];

    deg_kernel <<<(E + 255) / 256, 256>>>(dst, E);
    prep_kernel<<<(N + 255) / 256, 256>>>(N);
    fill_kernel<<<(E + 255) / 256, 256>>>(src, dst, E);
    gemm_kernel<<<(N + BM - 1) / BM, 256>>>(feature, W, N);
    {
        long long total = (long long)N * 32;
        agg_kernel<<<(int)((total + 255) / 256), 256>>>(bias, out, N);
    }
}

// round 12
// speedup vs baseline: 1.6818x; 1.6818x over previous
#include <cuda_runtime.h>
#include <cuda_bf16.h>
#include <cstdint>

#define D       128
#define MAXN    100000
#define MAXE    1600000

typedef unsigned long long u64;

// ---------------------------------------------------------------------------
// Scratch — static __device__ arrays, referenced ONLY inside kernels.
// (NEVER pass these as kernel args: host shadow symbol + GB300 ATS = silent
//  NVLink-C2C traffic — the round-2/4 5ms regression.)
// ---------------------------------------------------------------------------
__device__ int   g_deg[MAXN];
__device__ float g_scale[MAXN];                    // rsqrt(deg+1)
__device__ float g_inv[MAXN];                      // 1/max(deg,1)
__device__ int   g_rowstart[MAXN];
__device__ int   g_cursor[MAXN];
__device__ int   g_csr[MAXE];                      // src ids grouped by dst
__device__ int   g_total;                          // rowstart allocator
__device__ float g_pre[(size_t)MAXN * D];          // scale*(feat @ W)  (51.2MB)

// ---------------------------------------------------------------------------
// 0) In-degree histogram (g_deg zeroed by previous replay's agg tail)
// ---------------------------------------------------------------------------
__global__ void deg_kernel(const int* __restrict__ dst, int E) {
    int i = blockIdx.x * blockDim.x + threadIdx.x;
    if (i < E) atomicAdd(&g_deg[dst[i]], 1);
}

// ---------------------------------------------------------------------------
// 1) mini-prep: scale, inv, rowstart, cursor
// ---------------------------------------------------------------------------
__global__ void prep_kernel(int N) {
    int i = blockIdx.x * blockDim.x + threadIdx.x;
    if (i >= N) return;
    int dg = g_deg[i];
    g_scale[i] = rsqrtf((float)dg + 1.0f);
    g_inv[i]   = 1.0f / (float)(dg > 0 ? dg : 1);
    int rs = atomicAdd(&g_total, dg);
    g_rowstart[i] = rs;
    g_cursor[i]   = rs;
}

// ---------------------------------------------------------------------------
// 2) CSR fill: bucket src by dst
// ---------------------------------------------------------------------------
__global__ void fill_kernel(const int* __restrict__ src,
                            const int* __restrict__ dst, int E) {
    int i = blockIdx.x * blockDim.x + threadIdx.x;
    if (i < E) {
        int p = atomicAdd(&g_cursor[dst[i]], 1);
        g_csr[p] = src[i];
    }
}

// ---------------------------------------------------------------------------
// 3) GEMM: g_pre[m,:] = scale[m] * (feat[m,:] @ W)
//    Round-6 structure (proven) with BM=64/TM=4 for 3 CTAs/SM occupancy.
// ---------------------------------------------------------------------------
#define BM 64
#define BN 128
#define BK 16
#define TM 4
#define TN 8

__device__ __forceinline__ u64 pack2(float lo, float hi) {
    u64 r;
    asm("mov.b64 %0, {%1,%2};" : "=l"(r) : "f"(lo), "f"(hi));
    return r;
}
__device__ __forceinline__ float2 unpack2(u64 v) {
    float2 r;
    asm("mov.b64 {%0,%1}, %2;" : "=f"(r.x), "=f"(r.y) : "l"(v));
    return r;
}
__device__ __forceinline__ void fma2(u64& c, u64 a, u64 b) {
    asm("fma.rn.f32x2 %0, %1, %2, %3;" : "=l"(c) : "l"(a), "l"(b), "l"(c));
}

__global__ __launch_bounds__(256)
void gemm_kernel(const float* __restrict__ feat,
                 const float* __restrict__ W,
                 int n) {
    __shared__ __align__(16) float As[BK][BM + 4];   // 16*68*4  = 4.3KB
    __shared__ __align__(16) float Ws[BK][BN];       // 16*128*4 = 8.2KB

    int block_row = blockIdx.x * BM;
    int tid = threadIdx.x;
    int tx = tid & 15;          // 16 col groups of 8
    int ty = tid >> 4;          // 16 row groups of 4

    u64 c2[TM][TN / 2];
#pragma unroll
    for (int i = 0; i < TM; i++)
#pragma unroll
        for (int j = 0; j < TN / 2; j++) c2[i][j] = 0ULL;

    for (int k0 = 0; k0 < D; k0 += BK) {
        // A tile (BM x BK): 256 float4 units, one per thread, scale at load
        {
            int row = tid >> 2;             // 0..63
            int k4  = (tid & 3) * 4;        // 0,4,8,12
            int grow = block_row + row;
            float4 v = make_float4(0.f, 0.f, 0.f, 0.f);
            float sc = 0.f;
            if (grow < n) {
                v  = __ldg((const float4*)&feat[(size_t)grow * D + k0 + k4]);
                sc = g_scale[grow];
            }
            As[k4 + 0][row] = v.x * sc;
            As[k4 + 1][row] = v.y * sc;
            As[k4 + 2][row] = v.z * sc;
            As[k4 + 3][row] = v.w * sc;
        }
        // W tile (BK x BN): 512 float4 units, 2 per thread
#pragma unroll
        for (int it = 0; it < 2; it++) {
            int idx = tid + it * 256;
            int k  = idx >> 5;              // 0..15
            int c4 = (idx & 31) * 4;        // 0..124
            float4 v = __ldg((const float4*)&W[(size_t)(k0 + k) * D + c4]);
            *(float4*)&Ws[k][c4] = v;
        }
        __syncthreads();

#pragma unroll
        for (int k = 0; k < BK; k++) {
            float a[TM];
            u64 wv[TN / 2];
#pragma unroll
            for (int i = 0; i < TM; i++) a[i] = As[k][ty * TM + i];
            const u64* wp = (const u64*)&Ws[k][tx * TN];
#pragma unroll
            for (int j = 0; j < TN / 2; j++) wv[j] = wp[j];
#pragma unroll
            for (int i = 0; i < TM; i++) {
                u64 ap = pack2(a[i], a[i]);
#pragma unroll
                for (int j = 0; j < TN / 2; j++)
                    fma2(c2[i][j], ap, wv[j]);
            }
        }
        __syncthreads();
    }

    // Epilogue: scale already applied at A-load; plain store
#pragma unroll
    for (int i = 0; i < TM; i++) {
        int row = block_row + ty * TM + i;
        if (row < n) {
            float2 p0 = unpack2(c2[i][0]);
            float2 p1 = unpack2(c2[i][1]);
            float2 p2 = unpack2(c2[i][2]);
            float2 p3 = unpack2(c2[i][3]);
            int col = tx * TN;
            *(float4*)&g_pre[(size_t)row * D + col]     = make_float4(p0.x, p0.y, p1.x, p1.y);
            *(float4*)&g_pre[(size_t)row * D + col + 4] = make_float4(p2.x, p2.y, p3.x, p3.y);
        }
    }
}

// ---------------------------------------------------------------------------
// 4) Aggregation (gather): one warp per dst node; resets replay state.
// ---------------------------------------------------------------------------
__global__ __launch_bounds__(256)
void agg_kernel(const float* __restrict__ bias,
                float* __restrict__ out,
                int N) {
    int t = blockIdx.x * blockDim.x + threadIdx.x;
    int node = t >> 5;
    int lane = t & 31;
    if (node >= N) return;

    int start = g_rowstart[node];
    int deg   = g_deg[node];
    int end   = start + deg;

    const float4* pre4 = (const float4*)g_pre;

    float4 acc = make_float4(0.f, 0.f, 0.f, 0.f);

    int j = start;
    for (; j + 3 < end; j += 4) {
        int s0 = __ldg(&g_csr[j + 0]);
        int s1 = __ldg(&g_csr[j + 1]);
        int s2 = __ldg(&g_csr[j + 2]);
        int s3 = __ldg(&g_csr[j + 3]);
        float4 v0 = __ldg(pre4 + (size_t)s0 * 32 + lane);
        float4 v1 = __ldg(pre4 + (size_t)s1 * 32 + lane);
        float4 v2 = __ldg(pre4 + (size_t)s2 * 32 + lane);
        float4 v3 = __ldg(pre4 + (size_t)s3 * 32 + lane);
        acc.x += v0.x + v1.x + v2.x + v3.x;
        acc.y += v0.y + v1.y + v2.y + v3.y;
        acc.z += v0.z + v1.z + v2.z + v3.z;
        acc.w += v0.w + v1.w + v2.w + v3.w;
    }
    for (; j < end; j++) {
        int s = __ldg(&g_csr[j]);
        float4 v = __ldg(pre4 + (size_t)s * 32 + lane);
        acc.x += v.x; acc.y += v.y; acc.z += v.z; acc.w += v.w;
    }

    float iv = g_inv[node];
    float4 bb = __ldg((const float4*)bias + lane);
    float4 r;
    r.x = acc.x * iv + bb.x;
    r.y = acc.y * iv + bb.y;
    r.z = acc.z * iv + bb.z;
    r.w = acc.w * iv + bb.w;
    *((float4*)(out + (size_t)node * D) + lane) = r;

    // Reset per-replay state (node-private: this warp already consumed deg)
    if (lane == 0) g_deg[node] = 0;
    if (t == 0)    g_total = 0;
}

// ---------------------------------------------------------------------------
extern "C" void kernel_launch(void* const* d_in, const int* in_sizes, int n_in,
                              void* d_out, int out_size) {
    const float* feature = (const float*)d_in[0];
    const float* W       = (const float*)d_in[1];
    const float* bias    = (const float*)d_in[2];
    const int*   src     = (const int*)d_in[3];
    const int*   dst     = (const int*)d_in[4];
    float*       out     = (float*)d_out;

    int N = in_sizes[0] / D;
    int E = in_sizes[3];

    deg_kernel <<<(E + 255) / 256, 256>>>(dst, E);
    prep_kernel<<<(N + 255) / 256, 256>>>(N);
    fill_kernel<<<(E + 255) / 256, 256>>>(src, dst, E);
    gemm_kernel<<<(N + BM - 1) / BM, 256>>>(feature, W, N);
    {
        long long total = (long long)N * 32;
        agg_kernel<<<(int)((total + 255) / 256), 256>>>(bias, out, N);
    }
}

// round 13
// speedup vs baseline: 1.9048x; 1.1326x over previous
#include <cuda_runtime.h>
#include <cuda_bf16.h>
#include <cstdint>

#define D       128
#define MAXN    100000
#define MAXE    1600000

typedef unsigned long long u64;

// ---------------------------------------------------------------------------
// Scratch — static __device__ arrays, referenced ONLY inside kernels.
// (NEVER pass these as kernel args: host shadow symbol + GB300 ATS = silent
//  NVLink-C2C traffic — the round-2/4 5ms regression.)
// ---------------------------------------------------------------------------
__device__ int   g_deg[MAXN];
__device__ float g_scale[MAXN];                    // rsqrt(deg+1)
__device__ float g_inv[MAXN];                      // 1/max(deg,1)
__device__ int   g_rowstart[MAXN];
__device__ int   g_cursor[MAXN];
__device__ int   g_csr[MAXE];                      // src ids grouped by dst
__device__ int   g_total;                          // rowstart allocator
__device__ float g_pre[(size_t)MAXN * D];          // scale*(feat @ W)  (51.2MB)

// ---------------------------------------------------------------------------
// 0) In-degree histogram (g_deg zeroed by previous replay's agg tail)
// ---------------------------------------------------------------------------
__global__ void deg_kernel(const int* __restrict__ dst, int E) {
    int i = blockIdx.x * blockDim.x + threadIdx.x;
    if (i < E) atomicAdd(&g_deg[dst[i]], 1);
}

// ---------------------------------------------------------------------------
// 1) mini-prep: scale, inv, rowstart, cursor
// ---------------------------------------------------------------------------
__global__ void prep_kernel(int N) {
    int i = blockIdx.x * blockDim.x + threadIdx.x;
    if (i >= N) return;
    int dg = g_deg[i];
    g_scale[i] = rsqrtf((float)dg + 1.0f);
    g_inv[i]   = 1.0f / (float)(dg > 0 ? dg : 1);
    int rs = atomicAdd(&g_total, dg);
    g_rowstart[i] = rs;
    g_cursor[i]   = rs;
}

// ---------------------------------------------------------------------------
// 2) CSR fill: bucket src by dst
// ---------------------------------------------------------------------------
__global__ void fill_kernel(const int* __restrict__ src,
                            const int* __restrict__ dst, int E) {
    int i = blockIdx.x * blockDim.x + threadIdx.x;
    if (i < E) {
        int p = atomicAdd(&g_cursor[dst[i]], 1);
        g_csr[p] = src[i];
    }
}

// ---------------------------------------------------------------------------
// 3) GEMM: g_pre[m,:] = scale[m] * (feat[m,:] @ W)
//    Round-6 tiling (BM=128, BK=16, FFMA2). Fix: ALL inner-loop smem reads
//    are LDS.128 — W reads were 4-way bank-conflicted LDS.64 (the measured
//    L1-wavefront ceiling).  6 wf/warp/k vs 64 fma-cyc -> fma-bound.
// ---------------------------------------------------------------------------
#define BM 128
#define BN 128
#define BK 16
#define TM 8
#define TN 8

__device__ __forceinline__ u64 pack2(float lo, float hi) {
    u64 r;
    asm("mov.b64 %0, {%1,%2};" : "=l"(r) : "f"(lo), "f"(hi));
    return r;
}
__device__ __forceinline__ float2 unpack2(u64 v) {
    float2 r;
    asm("mov.b64 {%0,%1}, %2;" : "=f"(r.x), "=f"(r.y) : "l"(v));
    return r;
}
__device__ __forceinline__ void fma2(u64& c, u64 a, u64 b) {
    asm("fma.rn.f32x2 %0, %1, %2, %3;" : "=l"(c) : "l"(a), "l"(b), "l"(c));
}

__global__ __launch_bounds__(256)
void gemm_kernel(const float* __restrict__ feat,
                 const float* __restrict__ W,
                 int n) {
    __shared__ __align__(16) float As[BK][BM + 4];   // 16*132*4 = 8.4KB
    __shared__ __align__(16) float Ws[BK][BN];       // 16*128*4 = 8.2KB

    int block_row = blockIdx.x * BM;
    int tid = threadIdx.x;
    int tx = tid & 15;          // 16 col groups of 8
    int ty = tid >> 4;          // 16 row groups of 8

    u64 c2[TM][TN / 2];
#pragma unroll
    for (int i = 0; i < TM; i++)
#pragma unroll
        for (int j = 0; j < TN / 2; j++) c2[i][j] = 0ULL;

    for (int k0 = 0; k0 < D; k0 += BK) {
        // A tile (BM x BK) transposed-store, scale applied at load
#pragma unroll
        for (int it = 0; it < 2; it++) {
            int idx = tid + it * 256;
            int row = idx >> 2;             // 0..127
            int k4  = (idx & 3) * 4;        // 0,4,8,12
            int grow = block_row + row;
            float4 v = make_float4(0.f, 0.f, 0.f, 0.f);
            float sc = 0.f;
            if (grow < n) {
                v  = __ldg((const float4*)&feat[(size_t)grow * D + k0 + k4]);
                sc = g_scale[grow];
            }
            As[k4 + 0][row] = v.x * sc;
            As[k4 + 1][row] = v.y * sc;
            As[k4 + 2][row] = v.z * sc;
            As[k4 + 3][row] = v.w * sc;
        }
        // W tile (BK x BN)
#pragma unroll
        for (int it = 0; it < 2; it++) {
            int idx = tid + it * 256;
            int k  = idx >> 5;              // 0..15
            int c4 = (idx & 31) * 4;        // 0..124
            float4 v = __ldg((const float4*)&W[(size_t)(k0 + k) * D + c4]);
            *(float4*)&Ws[k][c4] = v;
        }
        __syncthreads();

#pragma unroll
        for (int k = 0; k < BK; k++) {
            // A: 2x LDS.128 (broadcast within warp: 2 distinct addrs -> 1 wf each)
            float4 a0 = *(const float4*)&As[k][ty * TM];
            float4 a1 = *(const float4*)&As[k][ty * TM + 4];
            // W: 2x LDS.128 (16 consecutive 16B chunks -> conflict-free, 2 wf each)
            ulonglong2 wA = *(const ulonglong2*)&Ws[k][tx * TN];
            ulonglong2 wB = *(const ulonglong2*)&Ws[k][tx * TN + 4];
            u64 wv0 = wA.x, wv1 = wA.y, wv2 = wB.x, wv3 = wB.y;

            u64 ap0 = pack2(a0.x, a0.x);
            u64 ap1 = pack2(a0.y, a0.y);
            u64 ap2 = pack2(a0.z, a0.z);
            u64 ap3 = pack2(a0.w, a0.w);
            u64 ap4 = pack2(a1.x, a1.x);
            u64 ap5 = pack2(a1.y, a1.y);
            u64 ap6 = pack2(a1.z, a1.z);
            u64 ap7 = pack2(a1.w, a1.w);

            fma2(c2[0][0], ap0, wv0); fma2(c2[0][1], ap0, wv1);
            fma2(c2[0][2], ap0, wv2); fma2(c2[0][3], ap0, wv3);
            fma2(c2[1][0], ap1, wv0); fma2(c2[1][1], ap1, wv1);
            fma2(c2[1][2], ap1, wv2); fma2(c2[1][3], ap1, wv3);
            fma2(c2[2][0], ap2, wv0); fma2(c2[2][1], ap2, wv1);
            fma2(c2[2][2], ap2, wv2); fma2(c2[2][3], ap2, wv3);
            fma2(c2[3][0], ap3, wv0); fma2(c2[3][1], ap3, wv1);
            fma2(c2[3][2], ap3, wv2); fma2(c2[3][3], ap3, wv3);
            fma2(c2[4][0], ap4, wv0); fma2(c2[4][1], ap4, wv1);
            fma2(c2[4][2], ap4, wv2); fma2(c2[4][3], ap4, wv3);
            fma2(c2[5][0], ap5, wv0); fma2(c2[5][1], ap5, wv1);
            fma2(c2[5][2], ap5, wv2); fma2(c2[5][3], ap5, wv3);
            fma2(c2[6][0], ap6, wv0); fma2(c2[6][1], ap6, wv1);
            fma2(c2[6][2], ap6, wv2); fma2(c2[6][3], ap6, wv3);
            fma2(c2[7][0], ap7, wv0); fma2(c2[7][1], ap7, wv1);
            fma2(c2[7][2], ap7, wv2); fma2(c2[7][3], ap7, wv3);
        }
        __syncthreads();
    }

    // Epilogue: scale already applied at A-load; plain store
#pragma unroll
    for (int i = 0; i < TM; i++) {
        int row = block_row + ty * TM + i;
        if (row < n) {
            float2 p0 = unpack2(c2[i][0]);
            float2 p1 = unpack2(c2[i][1]);
            float2 p2 = unpack2(c2[i][2]);
            float2 p3 = unpack2(c2[i][3]);
            int col = tx * TN;
            *(float4*)&g_pre[(size_t)row * D + col]     = make_float4(p0.x, p0.y, p1.x, p1.y);
            *(float4*)&g_pre[(size_t)row * D + col + 4] = make_float4(p2.x, p2.y, p3.x, p3.y);
        }
    }
}

// ---------------------------------------------------------------------------
// 4) Aggregation (gather): one warp per dst node; resets replay state.
// ---------------------------------------------------------------------------
__global__ __launch_bounds__(256)
void agg_kernel(const float* __restrict__ bias,
                float* __restrict__ out,
                int N) {
    int t = blockIdx.x * blockDim.x + threadIdx.x;
    int node = t >> 5;
    int lane = t & 31;
    if (node >= N) return;

    int start = g_rowstart[node];
    int deg   = g_deg[node];
    int end   = start + deg;

    const float4* pre4 = (const float4*)g_pre;

    float4 acc = make_float4(0.f, 0.f, 0.f, 0.f);

    int j = start;
    for (; j + 3 < end; j += 4) {
        int s0 = __ldg(&g_csr[j + 0]);
        int s1 = __ldg(&g_csr[j + 1]);
        int s2 = __ldg(&g_csr[j + 2]);
        int s3 = __ldg(&g_csr[j + 3]);
        float4 v0 = __ldg(pre4 + (size_t)s0 * 32 + lane);
        float4 v1 = __ldg(pre4 + (size_t)s1 * 32 + lane);
        float4 v2 = __ldg(pre4 + (size_t)s2 * 32 + lane);
        float4 v3 = __ldg(pre4 + (size_t)s3 * 32 + lane);
        acc.x += v0.x + v1.x + v2.x + v3.x;
        acc.y += v0.y + v1.y + v2.y + v3.y;
        acc.z += v0.z + v1.z + v2.z + v3.z;
        acc.w += v0.w + v1.w + v2.w + v3.w;
    }
    for (; j < end; j++) {
        int s = __ldg(&g_csr[j]);
        float4 v = __ldg(pre4 + (size_t)s * 32 + lane);
        acc.x += v.x; acc.y += v.y; acc.z += v.z; acc.w += v.w;
    }

    float iv = g_inv[node];
    float4 bb = __ldg((const float4*)bias + lane);
    float4 r;
    r.x = acc.x * iv + bb.x;
    r.y = acc.y * iv + bb.y;
    r.z = acc.z * iv + bb.z;
    r.w = acc.w * iv + bb.w;
    *((float4*)(out + (size_t)node * D) + lane) = r;

    // Reset per-replay state (node-private: this warp already consumed deg)
    if (lane == 0) g_deg[node] = 0;
    if (t == 0)    g_total = 0;
}

// ---------------------------------------------------------------------------
extern "C" void kernel_launch(void* const* d_in, const int* in_sizes, int n_in,
                              void* d_out, int out_size) {
    const float* feature = (const float*)d_in[0];
    const float* W       = (const float*)d_in[1];
    const float* bias    = (const float*)d_in[2];
    const int*   src     = (const int*)d_in[3];
    const int*   dst     = (const int*)d_in[4];
    float*       out     = (float*)d_out;

    int N = in_sizes[0] / D;
    int E = in_sizes[3];

    deg_kernel <<<(E + 255) / 256, 256>>>(dst, E);
    prep_kernel<<<(N + 255) / 256, 256>>>(N);
    fill_kernel<<<(E + 255) / 256, 256>>>(src, dst, E);
    gemm_kernel<<<(N + BM - 1) / BM, 256>>>(feature, W, N);
    {
        long long total = (long long)N * 32;
        agg_kernel<<<(int)((total + 255) / 256), 256>>>(bias, out, N);
    }
}

// round 14
// speedup vs baseline: 2.2002x; 1.1551x over previous
#include <cuda_runtime.h>
#include <cuda_bf16.h>
#include <cstdint>

#define D       128
#define MAXN    100000
#define MAXE    1600000

typedef unsigned long long u64;

// ---------------------------------------------------------------------------
// Scratch — static __device__ arrays, referenced ONLY inside kernels.
// (NEVER pass these as kernel args: host shadow symbol + GB300 ATS = silent
//  NVLink-C2C traffic — the round-2/4 5ms regression.)
// ---------------------------------------------------------------------------
__device__ int   g_deg[MAXN];
__device__ float g_scale[MAXN];                    // rsqrt(deg+1)
__device__ float g_inv[MAXN];                      // 1/max(deg,1)
__device__ int   g_rowstart[MAXN];
__device__ int   g_cursor[MAXN];
__device__ int   g_csr[MAXE];                      // src ids grouped by dst
__device__ int   g_total;                          // rowstart allocator
__device__ float g_pre[(size_t)MAXN * D];          // feat @ W  (unscaled, 51.2MB)

// ---------------------------------------------------------------------------
// 0) In-degree histogram (g_deg zeroed by previous replay's agg tail)
// ---------------------------------------------------------------------------
__global__ void deg_kernel(const int* __restrict__ dst, int E) {
    int i = blockIdx.x * blockDim.x + threadIdx.x;
    if (i < E) atomicAdd(&g_deg[dst[i]], 1);
}

// ---------------------------------------------------------------------------
// 1) mini-prep: scale, inv, rowstart, cursor
// ---------------------------------------------------------------------------
__global__ void prep_kernel(int N) {
    int i = blockIdx.x * blockDim.x + threadIdx.x;
    if (i >= N) return;
    int dg = g_deg[i];
    g_scale[i] = rsqrtf((float)dg + 1.0f);
    g_inv[i]   = 1.0f / (float)(dg > 0 ? dg : 1);
    int rs = atomicAdd(&g_total, dg);
    g_rowstart[i] = rs;
    g_cursor[i]   = rs;
}

// ---------------------------------------------------------------------------
// 2) CSR fill: bucket src by dst
// ---------------------------------------------------------------------------
__global__ void fill_kernel(const int* __restrict__ src,
                            const int* __restrict__ dst, int E) {
    int i = blockIdx.x * blockDim.x + threadIdx.x;
    if (i < E) {
        int p = atomicAdd(&g_cursor[dst[i]], 1);
        g_csr[p] = src[i];
    }
}

// ---------------------------------------------------------------------------
// 3) GEMM: g_pre[m,:] = feat[m,:] @ W    (NO scale — applied in agg, so this
//    kernel is independent of the degree chain and can run in parallel)
//    Proven round-6/13 tiling: BM=128, BK=16, FFMA2.
// ---------------------------------------------------------------------------
#define BM 128
#define BN 128
#define BK 16
#define TM 8
#define TN 8

__device__ __forceinline__ u64 pack2(float lo, float hi) {
    u64 r;
    asm("mov.b64 %0, {%1,%2};" : "=l"(r) : "f"(lo), "f"(hi));
    return r;
}
__device__ __forceinline__ float2 unpack2(u64 v) {
    float2 r;
    asm("mov.b64 {%0,%1}, %2;" : "=f"(r.x), "=f"(r.y) : "l"(v));
    return r;
}
__device__ __forceinline__ void fma2(u64& c, u64 a, u64 b) {
    asm("fma.rn.f32x2 %0, %1, %2, %3;" : "=l"(c) : "l"(a), "l"(b), "l"(c));
}

__global__ __launch_bounds__(256)
void gemm_kernel(const float* __restrict__ feat,
                 const float* __restrict__ W,
                 int n) {
    __shared__ __align__(16) float As[BK][BM + 4];
    __shared__ __align__(16) float Ws[BK][BN];

    int block_row = blockIdx.x * BM;
    int tid = threadIdx.x;
    int tx = tid & 15;
    int ty = tid >> 4;

    u64 c2[TM][TN / 2];
#pragma unroll
    for (int i = 0; i < TM; i++)
#pragma unroll
        for (int j = 0; j < TN / 2; j++) c2[i][j] = 0ULL;

    for (int k0 = 0; k0 < D; k0 += BK) {
#pragma unroll
        for (int it = 0; it < 2; it++) {
            int idx = tid + it * 256;
            int row = idx >> 2;
            int k4  = (idx & 3) * 4;
            int grow = block_row + row;
            float4 v = make_float4(0.f, 0.f, 0.f, 0.f);
            if (grow < n)
                v = __ldg((const float4*)&feat[(size_t)grow * D + k0 + k4]);
            As[k4 + 0][row] = v.x;
            As[k4 + 1][row] = v.y;
            As[k4 + 2][row] = v.z;
            As[k4 + 3][row] = v.w;
        }
#pragma unroll
        for (int it = 0; it < 2; it++) {
            int idx = tid + it * 256;
            int k  = idx >> 5;
            int c4 = (idx & 31) * 4;
            float4 v = __ldg((const float4*)&W[(size_t)(k0 + k) * D + c4]);
            *(float4*)&Ws[k][c4] = v;
        }
        __syncthreads();

#pragma unroll
        for (int k = 0; k < BK; k++) {
            float4 a0 = *(const float4*)&As[k][ty * TM];
            float4 a1 = *(const float4*)&As[k][ty * TM + 4];
            ulonglong2 wA = *(const ulonglong2*)&Ws[k][tx * TN];
            ulonglong2 wB = *(const ulonglong2*)&Ws[k][tx * TN + 4];
            u64 wv0 = wA.x, wv1 = wA.y, wv2 = wB.x, wv3 = wB.y;

            u64 ap0 = pack2(a0.x, a0.x);
            u64 ap1 = pack2(a0.y, a0.y);
            u64 ap2 = pack2(a0.z, a0.z);
            u64 ap3 = pack2(a0.w, a0.w);
            u64 ap4 = pack2(a1.x, a1.x);
            u64 ap5 = pack2(a1.y, a1.y);
            u64 ap6 = pack2(a1.z, a1.z);
            u64 ap7 = pack2(a1.w, a1.w);

            fma2(c2[0][0], ap0, wv0); fma2(c2[0][1], ap0, wv1);
            fma2(c2[0][2], ap0, wv2); fma2(c2[0][3], ap0, wv3);
            fma2(c2[1][0], ap1, wv0); fma2(c2[1][1], ap1, wv1);
            fma2(c2[1][2], ap1, wv2); fma2(c2[1][3], ap1, wv3);
            fma2(c2[2][0], ap2, wv0); fma2(c2[2][1], ap2, wv1);
            fma2(c2[2][2], ap2, wv2); fma2(c2[2][3], ap2, wv3);
            fma2(c2[3][0], ap3, wv0); fma2(c2[3][1], ap3, wv1);
            fma2(c2[3][2], ap3, wv2); fma2(c2[3][3], ap3, wv3);
            fma2(c2[4][0], ap4, wv0); fma2(c2[4][1], ap4, wv1);
            fma2(c2[4][2], ap4, wv2); fma2(c2[4][3], ap4, wv3);
            fma2(c2[5][0], ap5, wv0); fma2(c2[5][1], ap5, wv1);
            fma2(c2[5][2], ap5, wv2); fma2(c2[5][3], ap5, wv3);
            fma2(c2[6][0], ap6, wv0); fma2(c2[6][1], ap6, wv1);
            fma2(c2[6][2], ap6, wv2); fma2(c2[6][3], ap6, wv3);
            fma2(c2[7][0], ap7, wv0); fma2(c2[7][1], ap7, wv1);
            fma2(c2[7][2], ap7, wv2); fma2(c2[7][3], ap7, wv3);
        }
        __syncthreads();
    }

#pragma unroll
    for (int i = 0; i < TM; i++) {
        int row = block_row + ty * TM + i;
        if (row < n) {
            float2 p0 = unpack2(c2[i][0]);
            float2 p1 = unpack2(c2[i][1]);
            float2 p2 = unpack2(c2[i][2]);
            float2 p3 = unpack2(c2[i][3]);
            int col = tx * TN;
            *(float4*)&g_pre[(size_t)row * D + col]     = make_float4(p0.x, p0.y, p1.x, p1.y);
            *(float4*)&g_pre[(size_t)row * D + col + 4] = make_float4(p2.x, p2.y, p3.x, p3.y);
        }
    }
}

// ---------------------------------------------------------------------------
// 4) Aggregation (gather): one warp per dst node.
//    out[d,:] = inv[d] * sum_{s} scale[s] * g_pre[s,:] + bias
//    (scale folded here so gemm is degree-independent)
// ---------------------------------------------------------------------------
__global__ __launch_bounds__(256)
void agg_kernel(const float* __restrict__ bias,
                float* __restrict__ out,
                int N) {
    int t = blockIdx.x * blockDim.x + threadIdx.x;
    int node = t >> 5;
    int lane = t & 31;
    if (node >= N) return;

    int start = g_rowstart[node];
    int deg   = g_deg[node];
    int end   = start + deg;

    const float4* pre4 = (const float4*)g_pre;

    float4 acc = make_float4(0.f, 0.f, 0.f, 0.f);

    int j = start;
    for (; j + 3 < end; j += 4) {
        int s0 = __ldg(&g_csr[j + 0]);
        int s1 = __ldg(&g_csr[j + 1]);
        int s2 = __ldg(&g_csr[j + 2]);
        int s3 = __ldg(&g_csr[j + 3]);
        float c0 = __ldg(&g_scale[s0]);
        float c1 = __ldg(&g_scale[s1]);
        float c2 = __ldg(&g_scale[s2]);
        float c3 = __ldg(&g_scale[s3]);
        float4 v0 = __ldg(pre4 + (size_t)s0 * 32 + lane);
        float4 v1 = __ldg(pre4 + (size_t)s1 * 32 + lane);
        float4 v2 = __ldg(pre4 + (size_t)s2 * 32 + lane);
        float4 v3 = __ldg(pre4 + (size_t)s3 * 32 + lane);
        acc.x = fmaf(v0.x, c0, fmaf(v1.x, c1, fmaf(v2.x, c2, fmaf(v3.x, c3, acc.x))));
        acc.y = fmaf(v0.y, c0, fmaf(v1.y, c1, fmaf(v2.y, c2, fmaf(v3.y, c3, acc.y))));
        acc.z = fmaf(v0.z, c0, fmaf(v1.z, c1, fmaf(v2.z, c2, fmaf(v3.z, c3, acc.z))));
        acc.w = fmaf(v0.w, c0, fmaf(v1.w, c1, fmaf(v2.w, c2, fmaf(v3.w, c3, acc.w))));
    }
    for (; j < end; j++) {
        int s = __ldg(&g_csr[j]);
        float c = __ldg(&g_scale[s]);
        float4 v = __ldg(pre4 + (size_t)s * 32 + lane);
        acc.x = fmaf(v.x, c, acc.x);
        acc.y = fmaf(v.y, c, acc.y);
        acc.z = fmaf(v.z, c, acc.z);
        acc.w = fmaf(v.w, c, acc.w);
    }

    float iv = g_inv[node];
    float4 bb = __ldg((const float4*)bias + lane);
    float4 r;
    r.x = acc.x * iv + bb.x;
    r.y = acc.y * iv + bb.y;
    r.z = acc.z * iv + bb.z;
    r.w = acc.w * iv + bb.w;
    *((float4*)(out + (size_t)node * D) + lane) = r;

    // Reset per-replay state (node-private: this warp already consumed deg)
    if (lane == 0) g_deg[node] = 0;
    if (t == 0)    g_total = 0;
}

// ---------------------------------------------------------------------------
// Launch: fork/join so {deg, prep, fill} runs concurrently with the GEMM.
// Streams/events are host objects (no device memory) and the fork/join
// event pattern is capture-legal. Objects are created per call and not
// destroyed (kernel_launch runs only a handful of times; replays use the
// captured graph).
// ---------------------------------------------------------------------------
extern "C" void kernel_launch(void* const* d_in, const int* in_sizes, int n_in,
                              void* d_out, int out_size) {
    const float* feature = (const float*)d_in[0];
    const float* W       = (const float*)d_in[1];
    const float* bias    = (const float*)d_in[2];
    const int*   src     = (const int*)d_in[3];
    const int*   dst     = (const int*)d_in[4];
    float*       out     = (float*)d_out;

    int N = in_sizes[0] / D;
    int E = in_sizes[3];

    cudaStream_t s2;
    cudaEvent_t eFork, eJoin;
    cudaStreamCreateWithFlags(&s2, cudaStreamNonBlocking);
    cudaEventCreateWithFlags(&eFork, cudaEventDisableTiming);
    cudaEventCreateWithFlags(&eJoin, cudaEventDisableTiming);

    // fork: s2 branches off the main (capture) stream
    cudaEventRecord(eFork, 0);
    cudaStreamWaitEvent(s2, eFork, 0);

    // chain B (graph build) on s2
    deg_kernel <<<(E + 255) / 256, 256, 0, s2>>>(dst, E);
    prep_kernel<<<(N + 255) / 256, 256, 0, s2>>>(N);
    fill_kernel<<<(E + 255) / 256, 256, 0, s2>>>(src, dst, E);

    // chain A (GEMM) on the main stream, concurrent with chain B
    gemm_kernel<<<(N + BM - 1) / BM, 256>>>(feature, W, N);

    // join: main stream waits for chain B
    cudaEventRecord(eJoin, s2);
    cudaStreamWaitEvent(0, eJoin, 0);

    // agg consumes both chains
    {
        long long total = (long long)N * 32;
        agg_kernel<<<(int)((total + 255) / 256), 256>>>(bias, out, N);
    }
}